// round 2
// baseline (speedup 1.0000x reference)
#include <cuda_runtime.h>

#define N_NODES 50000
#define N_EDGES 800000
#define E_TOT   (N_EDGES + N_NODES)   // 850000 with self loops
#define HID     128
#define NHEAD   2
#define CH      64
#define G_GRAPHS 64
#define IN_DIM  4
#define OUT_DIM 7
#define NEG_SLOPE 0.2f
#define BN_EPS 1e-5f

// ---------------- scratch (device globals; no runtime allocation) ------------
__device__ float g_xl[N_NODES * HID];       // source-side transform
__device__ float g_xr[N_NODES * HID];       // target-side transform
__device__ float g_acc[N_NODES * HID];      // edge-aggregation accumulator / h buffer
__device__ float g_denom[N_NODES * NHEAD];  // softmax denominators (sum of p)
__device__ float g_sums[HID];               // BN channel sums
__device__ float g_sumsq[HID];              // BN channel sum of squares
__device__ float g_pooled[G_GRAPHS * HID];  // graph pooling sums
__device__ float g_cnt[G_GRAPHS];           // graph node counts

// ---------------- zeroing kernels --------------------------------------------
__global__ void k_zero_layer() {
    int stride = gridDim.x * blockDim.x;
    for (int i = blockIdx.x * blockDim.x + threadIdx.x; i < N_NODES * HID; i += stride) {
        g_acc[i] = 0.f;
        if (i < N_NODES * NHEAD) g_denom[i] = 0.f;
        if (i < HID) { g_sums[i] = 0.f; g_sumsq[i] = 0.f; }
    }
}

__global__ void k_zero_pool() {
    int i = blockIdx.x * blockDim.x + threadIdx.x;
    if (i < G_GRAPHS * HID) g_pooled[i] = 0.f;
    if (i < G_GRAPHS) g_cnt[i] = 0.f;
}

// ---------------- layer-1 input transform: xl = x@Wl1, xr = x@Wr1 ------------
__global__ void k_transform1(const float* __restrict__ x,
                             const float* __restrict__ Wl,
                             const float* __restrict__ Wr) {
    int c = threadIdx.x; // 128
    for (int n = blockIdx.x; n < N_NODES; n += gridDim.x) {
        float x0 = x[n * IN_DIM + 0];
        float x1 = x[n * IN_DIM + 1];
        float x2 = x[n * IN_DIM + 2];
        float x3 = x[n * IN_DIM + 3];
        g_xl[n * HID + c] = x0 * Wl[0 * HID + c] + x1 * Wl[1 * HID + c]
                          + x2 * Wl[2 * HID + c] + x3 * Wl[3 * HID + c];
        g_xr[n * HID + c] = x0 * Wr[0 * HID + c] + x1 * Wr[1 * HID + c]
                          + x2 * Wr[2 * HID + c] + x3 * Wr[3 * HID + c];
    }
}

// ---------------- fused edge pass: e -> p=exp(e) -> denom += p, acc += p*xl ---
// One warp per edge. Lanes 0-15 = head 0 channels 0..63, lanes 16-31 = head 1.
// Softmax max-shift skipped (scores O(1)); identical alpha after normalization.
__global__ void k_edge(const int* __restrict__ ei,
                       const float* __restrict__ att) {
    int warp = (blockIdx.x * blockDim.x + threadIdx.x) >> 5;
    if (warp >= E_TOT) return;
    int lane = threadIdx.x & 31;

    int src, dst;
    if (warp < N_EDGES) {
        src = ei[warp];
        dst = ei[N_EDGES + warp];
    } else {
        src = dst = warp - N_EDGES; // self loop
    }

    float4 a = *(const float4*)&g_xl[src * HID + lane * 4];
    float4 b = *(const float4*)&g_xr[dst * HID + lane * 4];
    float4 w = *(const float4*)&att[lane * 4];

    float m0 = a.x + b.x, m1 = a.y + b.y, m2 = a.z + b.z, m3 = a.w + b.w;
    m0 = m0 > 0.f ? m0 : NEG_SLOPE * m0;
    m1 = m1 > 0.f ? m1 : NEG_SLOPE * m1;
    m2 = m2 > 0.f ? m2 : NEG_SLOPE * m2;
    m3 = m3 > 0.f ? m3 : NEG_SLOPE * m3;

    float part = m0 * w.x + m1 * w.y + m2 * w.z + m3 * w.w;
    // butterfly reduce within each 16-lane head group (all lanes get the sum)
    part += __shfl_xor_sync(0xffffffffu, part, 8);
    part += __shfl_xor_sync(0xffffffffu, part, 4);
    part += __shfl_xor_sync(0xffffffffu, part, 2);
    part += __shfl_xor_sync(0xffffffffu, part, 1);

    float p = expf(part);

    if ((lane & 15) == 0)
        atomicAdd(&g_denom[dst * NHEAD + (lane >> 4)], p);

    float r0 = p * a.x, r1 = p * a.y, r2 = p * a.z, r3 = p * a.w;
    float* dptr = &g_acc[dst * HID + lane * 4];
    asm volatile("red.global.add.v4.f32 [%0], {%1,%2,%3,%4};"
                 :: "l"(dptr), "f"(r0), "f"(r1), "f"(r2), "f"(r3)
                 : "memory");
}

// ---------------- per-node finish: divide by denom, add bias, BN stats -------
__global__ void k_node_finish(const float* __restrict__ bias) {
    int c = threadIdx.x; // 128
    float bc = bias[c];
    float s = 0.f, s2 = 0.f;
    for (int n = blockIdx.x; n < N_NODES; n += gridDim.x) {
        float d = g_denom[n * NHEAD + (c >> 6)];
        float v = g_acc[n * HID + c] / d + bc;
        g_acc[n * HID + c] = v;
        s += v; s2 += v * v;
    }
    atomicAdd(&g_sums[c], s);
    atomicAdd(&g_sumsq[c], s2);
}

// ---------------- BN (train-mode, biased var) + ReLU, in-place on g_acc ------
__global__ void k_bn_relu(const float* __restrict__ gamma,
                          const float* __restrict__ beta) {
    int c = threadIdx.x;
    const float invN = 1.f / (float)N_NODES;
    float mu  = g_sums[c] * invN;
    float var = g_sumsq[c] * invN - mu * mu;
    float sc  = gamma[c] * rsqrtf(var + BN_EPS);
    float sh  = beta[c] - mu * sc;
    for (int n = blockIdx.x; n < N_NODES; n += gridDim.x) {
        float v = g_acc[n * HID + c] * sc + sh;
        g_acc[n * HID + c] = v > 0.f ? v : 0.f;
    }
}

// ---------------- layer-2 transforms: [g_xl | g_xr] = g_acc @ [Wl2 | Wr2] ----
// Block: 256 threads, 32 rows x 256 cols, 8x4 register tile per thread.
__global__ void k_gemm2(const float* __restrict__ Wl,
                        const float* __restrict__ Wr) {
    __shared__ float hT[32 * 32];    // 32 rows x 32 k
    __shared__ float wT[32 * 256];   // 32 k x 256 cols
    int tid = threadIdx.x;
    int row0 = blockIdx.x * 32;
    int cg = tid & 63;   // 64 col groups of 4
    int rg = tid >> 6;   // 4 row groups of 8
    int c0 = cg * 4;

    float acc[8][4];
    #pragma unroll
    for (int r = 0; r < 8; r++)
        #pragma unroll
        for (int j = 0; j < 4; j++) acc[r][j] = 0.f;

    for (int k0 = 0; k0 < HID; k0 += 32) {
        // load h tile (clamp row for the partial last block; writes are guarded)
        {
            int r = tid >> 3;
            int kk4 = (tid & 7) << 2;
            int rr = row0 + r; if (rr >= N_NODES) rr = N_NODES - 1;
            float4 v = *(const float4*)&g_acc[rr * HID + k0 + kk4];
            *(float4*)&hT[r * 32 + kk4] = v;
        }
        // load W tile: 2048 float4 units, 8 per thread
        #pragma unroll
        for (int i = 0; i < 8; i++) {
            int u = tid + i * 256;
            int kk = u >> 6;
            int c4 = (u & 63) << 2;
            const float* src = (c4 < HID) ? &Wl[(k0 + kk) * HID + c4]
                                          : &Wr[(k0 + kk) * HID + (c4 - HID)];
            *(float4*)&wT[kk * 256 + c4] = *(const float4*)src;
        }
        __syncthreads();
        #pragma unroll
        for (int kk = 0; kk < 32; kk++) {
            float4 b = *(float4*)&wT[kk * 256 + c0];
            #pragma unroll
            for (int r = 0; r < 8; r++) {
                float a = hT[(rg * 8 + r) * 32 + kk];
                acc[r][0] += a * b.x;
                acc[r][1] += a * b.y;
                acc[r][2] += a * b.z;
                acc[r][3] += a * b.w;
            }
        }
        __syncthreads();
    }

    float* dbase = (c0 < HID) ? g_xl : g_xr;
    int cc = (c0 < HID) ? c0 : c0 - HID;
    #pragma unroll
    for (int r = 0; r < 8; r++) {
        int row = row0 + rg * 8 + r;
        if (row < N_NODES)
            *(float4*)&dbase[row * HID + cc] =
                make_float4(acc[r][0], acc[r][1], acc[r][2], acc[r][3]);
    }
}

// ---------------- global mean pool (sums + counts) ---------------------------
__global__ void k_pool(const int* __restrict__ batch) {
    int warp = (blockIdx.x * blockDim.x + threadIdx.x) >> 5;
    if (warp >= N_NODES) return;
    int lane = threadIdx.x & 31;
    int g = batch[warp];
    float4 v = *(const float4*)&g_acc[warp * HID + lane * 4];
    float* dptr = &g_pooled[g * HID + lane * 4];
    asm volatile("red.global.add.v4.f32 [%0], {%1,%2,%3,%4};"
                 :: "l"(dptr), "f"(v.x), "f"(v.y), "f"(v.z), "f"(v.w)
                 : "memory");
    if (lane == 0) atomicAdd(&g_cnt[g], 1.f);
}

// ---------------- MLP head ----------------------------------------------------
__global__ void k_head(const float* __restrict__ W3, const float* __restrict__ b3,
                       const float* __restrict__ W4, const float* __restrict__ b4,
                       float* __restrict__ out) {
    __shared__ float z[CH];
    int g = blockIdx.x;   // 64 graphs
    int t = threadIdx.x;  // 64 threads
    float cnt = g_cnt[g];
    float inv = 1.f / (cnt > 1.f ? cnt : 1.f);
    float a = b3[t];
    #pragma unroll 4
    for (int k = 0; k < HID; k++)
        a += (g_pooled[g * HID + k] * inv) * W3[k * CH + t];
    z[t] = a > 0.f ? a : 0.f;
    __syncthreads();
    if (t < OUT_DIM) {
        float o = b4[t];
        #pragma unroll
        for (int k = 0; k < CH; k++)
            o += z[k] * W4[k * OUT_DIM + t];
        out[g * OUT_DIM + t] = o;
    }
}

// ---------------- launch ------------------------------------------------------
extern "C" void kernel_launch(void* const* d_in, const int* in_sizes, int n_in,
                              void* d_out, int out_size) {
    const float* x     = (const float*)d_in[0];
    const int*   ei    = (const int*)d_in[1];    // int32 (JAX x64 disabled)
    const int*   batch = (const int*)d_in[2];
    const float* Wl1 = (const float*)d_in[3];
    const float* Wr1 = (const float*)d_in[4];
    const float* att1= (const float*)d_in[5];
    const float* b1  = (const float*)d_in[6];
    const float* g1  = (const float*)d_in[7];
    const float* be1 = (const float*)d_in[8];
    const float* Wl2 = (const float*)d_in[9];
    const float* Wr2 = (const float*)d_in[10];
    const float* att2= (const float*)d_in[11];
    const float* b2  = (const float*)d_in[12];
    const float* g2  = (const float*)d_in[13];
    const float* be2 = (const float*)d_in[14];
    const float* W3  = (const float*)d_in[15];
    const float* b3  = (const float*)d_in[16];
    const float* W4  = (const float*)d_in[17];
    const float* b4  = (const float*)d_in[18];
    float* out = (float*)d_out;

    const int edge_blocks = (E_TOT + 7) / 8;     // warp per edge, 8 warps/block
    const int node_warp_blocks = (N_NODES + 7) / 8;

    // ---- layer 1 ----
    k_transform1<<<2048, 128>>>(x, Wl1, Wr1);
    k_zero_layer<<<2048, 256>>>();
    k_edge<<<edge_blocks, 256>>>(ei, att1);
    k_node_finish<<<512, 128>>>(b1);
    k_bn_relu<<<512, 128>>>(g1, be1);

    // ---- layer 2 transforms (reads g_acc, writes g_xl/g_xr) ----
    k_gemm2<<<(N_NODES + 31) / 32, 256>>>(Wl2, Wr2);

    // ---- layer 2 ----
    k_zero_layer<<<2048, 256>>>();
    k_edge<<<edge_blocks, 256>>>(ei, att2);
    k_node_finish<<<512, 128>>>(b2);
    k_bn_relu<<<512, 128>>>(g2, be2);

    // ---- pool + head ----
    k_zero_pool<<<(G_GRAPHS * HID + 255) / 256, 256>>>();
    k_pool<<<node_warp_blocks, 256>>>(batch);
    k_head<<<G_GRAPHS, CH>>>(W3, b3, W4, b4, out);
}

// round 3
// speedup vs baseline: 1.0220x; 1.0220x over previous
#include <cuda_runtime.h>

#define N_NODES 50000
#define N_EDGES 800000
#define E_TOT   (N_EDGES + N_NODES)   // 850000 with self loops
#define HID     128
#define NHEAD   2
#define CH      64
#define G_GRAPHS 64
#define IN_DIM  4
#define OUT_DIM 7
#define NEG_SLOPE 0.2f
#define BN_EPS 1e-5f

// ---------------- scratch (device globals; no runtime allocation) ------------
__device__ float g_xl[N_NODES * HID];        // source-side transform
__device__ float g_xr[N_NODES * HID];        // target-side transform
__device__ float g_acc1[N_NODES * HID];      // layer-1 edge accumulator
__device__ float g_acc2[N_NODES * HID];      // layer-2 edge accumulator
__device__ float g_denom1[N_NODES * NHEAD];
__device__ float g_denom2[N_NODES * NHEAD];
__device__ float g_sums[HID];                // BN channel sums
__device__ float g_sumsq[HID];               // BN channel sum of squares
__device__ float g_bn_sc[HID];               // BN scale (gamma*rsqrt(var+eps))
__device__ float g_bn_sh[HID];               // BN shift (beta - mu*sc)
__device__ float g_pooled[G_GRAPHS * HID];
__device__ float g_cnt[G_GRAPHS];

#define FMA2(d, a, b, c) \
    asm("fma.rn.f32x2 %0, %1, %2, %3;" : "=l"(d) : "l"(a), "l"(b), "l"(c))

union F2U { unsigned long long u; float2 f; };

// ---------------- layer-1 transform + all zero-init ---------------------------
__global__ void k_transform1(const float* __restrict__ x,
                             const float* __restrict__ Wl,
                             const float* __restrict__ Wr) {
    int c = threadIdx.x; // 128
    float wl0 = Wl[0 * HID + c], wl1 = Wl[1 * HID + c];
    float wl2 = Wl[2 * HID + c], wl3 = Wl[3 * HID + c];
    float wr0 = Wr[0 * HID + c], wr1 = Wr[1 * HID + c];
    float wr2 = Wr[2 * HID + c], wr3 = Wr[3 * HID + c];
    for (int n = blockIdx.x; n < N_NODES; n += gridDim.x) {
        float x0 = x[n * IN_DIM + 0];
        float x1 = x[n * IN_DIM + 1];
        float x2 = x[n * IN_DIM + 2];
        float x3 = x[n * IN_DIM + 3];
        g_xl[n * HID + c] = x0 * wl0 + x1 * wl1 + x2 * wl2 + x3 * wl3;
        g_xr[n * HID + c] = x0 * wr0 + x1 * wr1 + x2 * wr2 + x3 * wr3;
        g_acc1[n * HID + c] = 0.f;
        g_acc2[n * HID + c] = 0.f;
        if (c < NHEAD) {
            g_denom1[n * NHEAD + c] = 0.f;
            g_denom2[n * NHEAD + c] = 0.f;
        }
    }
    if (blockIdx.x == 0) {
        g_sums[c] = 0.f; g_sumsq[c] = 0.f;
        for (int i = c; i < G_GRAPHS * HID; i += HID) g_pooled[i] = 0.f;
        if (c < G_GRAPHS) g_cnt[c] = 0.f;
    }
}

// ---------------- fused edge pass: p=exp(e); denom += p; acc += p*xl ----------
// One warp per edge. Lanes 0-15 = head 0, lanes 16-31 = head 1 (64 ch each).
// Softmax max-shift skipped (scores O(1)); identical alpha after normalization.
__global__ void k_edge(const int* __restrict__ ei,
                       const float* __restrict__ att, int layer) {
    int warp = (blockIdx.x * blockDim.x + threadIdx.x) >> 5;
    if (warp >= E_TOT) return;
    int lane = threadIdx.x & 31;

    float* acc   = layer ? g_acc2   : g_acc1;
    float* denom = layer ? g_denom2 : g_denom1;

    int src, dst;
    if (warp < N_EDGES) {
        src = __ldg(&ei[warp]);
        dst = __ldg(&ei[N_EDGES + warp]);
    } else {
        src = dst = warp - N_EDGES; // self loop
    }

    float4 a = *(const float4*)&g_xl[src * HID + lane * 4];
    float4 b = *(const float4*)&g_xr[dst * HID + lane * 4];
    float4 w = *(const float4*)&att[lane * 4];

    float m0 = a.x + b.x, m1 = a.y + b.y, m2 = a.z + b.z, m3 = a.w + b.w;
    m0 = m0 > 0.f ? m0 : NEG_SLOPE * m0;
    m1 = m1 > 0.f ? m1 : NEG_SLOPE * m1;
    m2 = m2 > 0.f ? m2 : NEG_SLOPE * m2;
    m3 = m3 > 0.f ? m3 : NEG_SLOPE * m3;

    float part = m0 * w.x + m1 * w.y + m2 * w.z + m3 * w.w;
    part += __shfl_xor_sync(0xffffffffu, part, 8);
    part += __shfl_xor_sync(0xffffffffu, part, 4);
    part += __shfl_xor_sync(0xffffffffu, part, 2);
    part += __shfl_xor_sync(0xffffffffu, part, 1);

    float p = __expf(part);

    if ((lane & 15) == 0)
        atomicAdd(&denom[dst * NHEAD + (lane >> 4)], p);

    float r0 = p * a.x, r1 = p * a.y, r2 = p * a.z, r3 = p * a.w;
    float* dptr = &acc[dst * HID + lane * 4];
    asm volatile("red.global.add.v4.f32 [%0], {%1,%2,%3,%4};"
                 :: "l"(dptr), "f"(r0), "f"(r1), "f"(r2), "f"(r3)
                 : "memory");
}

// ---------------- per-node finish: divide by denom, add bias, BN stats -------
// 256 threads = 2 nodes per block-iteration; channel = tid & 127.
__global__ void k_node_finish(const float* __restrict__ bias, int layer) {
    __shared__ float s_s[256], s_s2[256];
    float* acc         = layer ? g_acc2   : g_acc1;
    const float* denom = layer ? g_denom2 : g_denom1;
    int tid = threadIdx.x;
    int c = tid & 127;
    int sub = tid >> 7;
    float bc = bias[c];
    int h = c >> 6;
    float s = 0.f, s2 = 0.f;
    for (int n = blockIdx.x * 2 + sub; n < N_NODES; n += gridDim.x * 2) {
        float d = denom[n * NHEAD + h];
        float inv = __fdividef(1.f, d);
        float v = fmaf(acc[n * HID + c], inv, bc);
        acc[n * HID + c] = v;
        s += v; s2 += v * v;
    }
    s_s[tid] = s; s_s2[tid] = s2;
    __syncthreads();
    if (sub == 0) {
        atomicAdd(&g_sums[c],  s_s[tid] + s_s[tid + 128]);
        atomicAdd(&g_sumsq[c], s_s2[tid] + s_s2[tid + 128]);
    }
}

// ---------------- BN prep: compute scale/shift, re-zero stats ----------------
__global__ void k_bn_prep(const float* __restrict__ gamma,
                          const float* __restrict__ beta) {
    int c = threadIdx.x; // 128
    const float invN = 1.f / (float)N_NODES;
    float mu  = g_sums[c] * invN;
    float var = g_sumsq[c] * invN - mu * mu;
    float sc  = gamma[c] * rsqrtf(var + BN_EPS);
    g_bn_sc[c] = sc;
    g_bn_sh[c] = beta[c] - mu * sc;
    g_sums[c] = 0.f;
    g_sumsq[c] = 0.f;
}

// ---------------- layer-2 transforms with fused BN1+ReLU on the A load -------
// [g_xl | g_xr] = relu(bn(g_acc1)) @ [Wl2 | Wr2]
// Block 256 thr, tile 64 rows x 128 cols, thread tile 8x4 via f32x2 FFMA2.
__global__ void k_gemm2(const float* __restrict__ Wl,
                        const float* __restrict__ Wr) {
    __shared__ __align__(16) float sA[32][68];    // [k][row], padded
    __shared__ __align__(16) float wTd[32][256];  // [k][col duplicated pairs]

    int tid = threadIdx.x;
    int row0 = blockIdx.x * 64;
    const float* W = blockIdx.y ? Wr : Wl;
    float* dst = blockIdx.y ? g_xr : g_xl;

    int cg = tid & 31;   // 32 col groups of 4
    int rg = tid >> 5;   // 8 row groups of 8
    int c0 = cg * 4;
    int rg8 = rg * 8;

    unsigned long long acc[4][4];
    #pragma unroll
    for (int i = 0; i < 4; i++)
        #pragma unroll
        for (int j = 0; j < 4; j++) acc[i][j] = 0ull;

    for (int k0 = 0; k0 < HID; k0 += 32) {
        // ---- load A tile (transpose + BN + ReLU) ----
        #pragma unroll
        for (int half = 0; half < 2; half++) {
            int u = tid + half * 256;
            int r = u >> 3;             // 0..63
            int k4 = (u & 7) * 4;
            int row = row0 + r;
            int rr = row < N_NODES ? row : N_NODES - 1;
            float4 v = *(const float4*)&g_acc1[rr * HID + k0 + k4];
            float4 sc = *(const float4*)&g_bn_sc[k0 + k4];
            float4 sh = *(const float4*)&g_bn_sh[k0 + k4];
            float t0 = fmaf(v.x, sc.x, sh.x); t0 = t0 > 0.f ? t0 : 0.f;
            float t1 = fmaf(v.y, sc.y, sh.y); t1 = t1 > 0.f ? t1 : 0.f;
            float t2 = fmaf(v.z, sc.z, sh.z); t2 = t2 > 0.f ? t2 : 0.f;
            float t3 = fmaf(v.w, sc.w, sh.w); t3 = t3 > 0.f ? t3 : 0.f;
            sA[k4 + 0][r] = t0;
            sA[k4 + 1][r] = t1;
            sA[k4 + 2][r] = t2;
            sA[k4 + 3][r] = t3;
        }
        // ---- load B tile, duplicated pairs ----
        #pragma unroll
        for (int i = 0; i < 4; i++) {
            int u = tid + i * 256;
            int kk = u >> 5;
            int c4 = (u & 31) * 4;
            float4 w = *(const float4*)&W[(k0 + kk) * HID + c4];
            *(float4*)&wTd[kk][c4 * 2]     = make_float4(w.x, w.x, w.y, w.y);
            *(float4*)&wTd[kk][c4 * 2 + 4] = make_float4(w.z, w.z, w.w, w.w);
        }
        __syncthreads();
        #pragma unroll
        for (int kk = 0; kk < 32; kk++) {
            ulonglong2 A0 = *(ulonglong2*)&sA[kk][rg8];         // rows {0,1},{2,3}
            ulonglong2 A1 = *(ulonglong2*)&sA[kk][rg8 + 4];     // rows {4,5},{6,7}
            ulonglong2 B0 = *(ulonglong2*)&wTd[kk][c0 * 2];     // {b0,b0},{b1,b1}
            ulonglong2 B1 = *(ulonglong2*)&wTd[kk][c0 * 2 + 4]; // {b2,b2},{b3,b3}
            FMA2(acc[0][0], A0.x, B0.x, acc[0][0]);
            FMA2(acc[0][1], A0.x, B0.y, acc[0][1]);
            FMA2(acc[0][2], A0.x, B1.x, acc[0][2]);
            FMA2(acc[0][3], A0.x, B1.y, acc[0][3]);
            FMA2(acc[1][0], A0.y, B0.x, acc[1][0]);
            FMA2(acc[1][1], A0.y, B0.y, acc[1][1]);
            FMA2(acc[1][2], A0.y, B1.x, acc[1][2]);
            FMA2(acc[1][3], A0.y, B1.y, acc[1][3]);
            FMA2(acc[2][0], A1.x, B0.x, acc[2][0]);
            FMA2(acc[2][1], A1.x, B0.y, acc[2][1]);
            FMA2(acc[2][2], A1.x, B1.x, acc[2][2]);
            FMA2(acc[2][3], A1.x, B1.y, acc[2][3]);
            FMA2(acc[3][0], A1.y, B0.x, acc[3][0]);
            FMA2(acc[3][1], A1.y, B0.y, acc[3][1]);
            FMA2(acc[3][2], A1.y, B1.x, acc[3][2]);
            FMA2(acc[3][3], A1.y, B1.y, acc[3][3]);
        }
        __syncthreads();
    }

    #pragma unroll
    for (int rp = 0; rp < 4; rp++) {
        F2U p0, p1, p2, p3;
        p0.u = acc[rp][0]; p1.u = acc[rp][1];
        p2.u = acc[rp][2]; p3.u = acc[rp][3];
        int row_e = row0 + rg8 + rp * 2;
        if (row_e < N_NODES)
            *(float4*)&dst[row_e * HID + c0] =
                make_float4(p0.f.x, p1.f.x, p2.f.x, p3.f.x);
        if (row_e + 1 < N_NODES)
            *(float4*)&dst[(row_e + 1) * HID + c0] =
                make_float4(p0.f.y, p1.f.y, p2.f.y, p3.f.y);
    }
}

// ---------------- global mean pool with fused BN2 + ReLU ---------------------
__global__ void k_pool(const int* __restrict__ batch) {
    int gwarp = (blockIdx.x * blockDim.x + threadIdx.x) >> 5;
    int nwarps = (gridDim.x * blockDim.x) >> 5;
    int lane = threadIdx.x & 31;
    float4 sc = *(const float4*)&g_bn_sc[lane * 4];
    float4 sh = *(const float4*)&g_bn_sh[lane * 4];
    for (int n = gwarp; n < N_NODES; n += nwarps) {
        int g = __ldg(&batch[n]);
        float4 v = *(const float4*)&g_acc2[n * HID + lane * 4];
        float v0 = fmaf(v.x, sc.x, sh.x); v0 = v0 > 0.f ? v0 : 0.f;
        float v1 = fmaf(v.y, sc.y, sh.y); v1 = v1 > 0.f ? v1 : 0.f;
        float v2 = fmaf(v.z, sc.z, sh.z); v2 = v2 > 0.f ? v2 : 0.f;
        float v3 = fmaf(v.w, sc.w, sh.w); v3 = v3 > 0.f ? v3 : 0.f;
        float* dptr = &g_pooled[g * HID + lane * 4];
        asm volatile("red.global.add.v4.f32 [%0], {%1,%2,%3,%4};"
                     :: "l"(dptr), "f"(v0), "f"(v1), "f"(v2), "f"(v3)
                     : "memory");
        if (lane == 0) atomicAdd(&g_cnt[g], 1.f);
    }
}

// ---------------- MLP head ----------------------------------------------------
__global__ void k_head(const float* __restrict__ W3, const float* __restrict__ b3,
                       const float* __restrict__ W4, const float* __restrict__ b4,
                       float* __restrict__ out) {
    __shared__ float z[CH];
    int g = blockIdx.x;   // 64 graphs
    int t = threadIdx.x;  // 64 threads
    float cnt = g_cnt[g];
    float inv = 1.f / (cnt > 1.f ? cnt : 1.f);
    float a = b3[t];
    #pragma unroll 4
    for (int k = 0; k < HID; k++)
        a += (g_pooled[g * HID + k] * inv) * W3[k * CH + t];
    z[t] = a > 0.f ? a : 0.f;
    __syncthreads();
    if (t < OUT_DIM) {
        float o = b4[t];
        #pragma unroll
        for (int k = 0; k < CH; k++)
            o += z[k] * W4[k * OUT_DIM + t];
        out[g * OUT_DIM + t] = o;
    }
}

// ---------------- launch ------------------------------------------------------
extern "C" void kernel_launch(void* const* d_in, const int* in_sizes, int n_in,
                              void* d_out, int out_size) {
    const float* x     = (const float*)d_in[0];
    const int*   ei    = (const int*)d_in[1];    // int32 (JAX x64 disabled)
    const int*   batch = (const int*)d_in[2];
    const float* Wl1 = (const float*)d_in[3];
    const float* Wr1 = (const float*)d_in[4];
    const float* att1= (const float*)d_in[5];
    const float* b1  = (const float*)d_in[6];
    const float* g1  = (const float*)d_in[7];
    const float* be1 = (const float*)d_in[8];
    const float* Wl2 = (const float*)d_in[9];
    const float* Wr2 = (const float*)d_in[10];
    const float* att2= (const float*)d_in[11];
    const float* b2  = (const float*)d_in[12];
    const float* g2  = (const float*)d_in[13];
    const float* be2 = (const float*)d_in[14];
    const float* W3  = (const float*)d_in[15];
    const float* b3  = (const float*)d_in[16];
    const float* W4  = (const float*)d_in[17];
    const float* b4  = (const float*)d_in[18];
    float* out = (float*)d_out;

    const int edge_blocks = (E_TOT + 7) / 8;     // warp per edge, 8 warps/block

    // ---- layer 1 ----
    k_transform1<<<2048, 128>>>(x, Wl1, Wr1);
    k_edge<<<edge_blocks, 256>>>(ei, att1, 0);
    k_node_finish<<<2048, 256>>>(b1, 0);
    k_bn_prep<<<1, 128>>>(g1, be1);

    // ---- layer 2 transforms (BN1+ReLU fused into A load) ----
    dim3 ggrid((N_NODES + 63) / 64, 2);
    k_gemm2<<<ggrid, 256>>>(Wl2, Wr2);

    // ---- layer 2 ----
    k_edge<<<edge_blocks, 256>>>(ei, att2, 1);
    k_node_finish<<<2048, 256>>>(b2, 1);
    k_bn_prep<<<1, 128>>>(g2, be2);

    // ---- pool + head (BN2+ReLU fused into pool) ----
    k_pool<<<512, 256>>>(batch);
    k_head<<<G_GRAPHS, CH>>>(W3, b3, W4, b4, out);
}

// round 6
// speedup vs baseline: 1.2447x; 1.2179x over previous
#include <cuda_runtime.h>

#define N_NODES 50000
#define N_EDGES 800000
#define HID     128
#define NHEAD   2
#define CH      64
#define G_GRAPHS 64
#define IN_DIM  4
#define OUT_DIM 7
#define NEG_SLOPE 0.2f
#define BN_EPS 1e-5f

// ---------------- scratch (device globals; no runtime allocation) ------------
__device__ float g_xl[N_NODES * HID];        // source-side transform
__device__ float g_xr[N_NODES * HID];        // target-side transform
__device__ float g_acc1[N_NODES * HID];      // layer-1 output h1 (pre-BN)
__device__ float g_acc2[N_NODES * HID];      // layer-2 output h2 (pre-BN)
__device__ int   g_deg[N_NODES];             // in-degree histogram
__device__ int   g_rowptr[N_NODES + 1];      // CSR row pointers (by dst)
__device__ int   g_cursor[N_NODES];          // fill cursors (zeroed separately)
__device__ int   g_csr_src[N_EDGES];         // CSR: src node per edge
__device__ float g_sums[HID];                // BN channel sums
__device__ float g_sumsq[HID];               // BN channel sum of squares
__device__ float g_bn_sc[HID];               // BN scale
__device__ float g_bn_sh[HID];               // BN shift
__device__ float g_pooled[G_GRAPHS * HID];
__device__ float g_cnt[G_GRAPHS];

#define FMA2(d, a, b, c) \
    asm("fma.rn.f32x2 %0, %1, %2, %3;" : "=l"(d) : "l"(a), "l"(b), "l"(c))

union F2U { unsigned long long u; float2 f; };

// ---------------- layer-1 transform + zero-init of small state ---------------
__global__ void k_transform1(const float* __restrict__ x,
                             const float* __restrict__ Wl,
                             const float* __restrict__ Wr) {
    int c = threadIdx.x; // 128
    float wl0 = Wl[0 * HID + c], wl1 = Wl[1 * HID + c];
    float wl2 = Wl[2 * HID + c], wl3 = Wl[3 * HID + c];
    float wr0 = Wr[0 * HID + c], wr1 = Wr[1 * HID + c];
    float wr2 = Wr[2 * HID + c], wr3 = Wr[3 * HID + c];
    for (int n = blockIdx.x; n < N_NODES; n += gridDim.x) {
        float x0 = x[n * IN_DIM + 0];
        float x1 = x[n * IN_DIM + 1];
        float x2 = x[n * IN_DIM + 2];
        float x3 = x[n * IN_DIM + 3];
        g_xl[n * HID + c] = x0 * wl0 + x1 * wl1 + x2 * wl2 + x3 * wl3;
        g_xr[n * HID + c] = x0 * wr0 + x1 * wr1 + x2 * wr2 + x3 * wr3;
        if (c == 0) g_deg[n] = 0;
        if (c == 1) g_cursor[n] = 0;
    }
    if (blockIdx.x == 0) {
        g_sums[c] = 0.f; g_sumsq[c] = 0.f;
        for (int i = c; i < G_GRAPHS * HID; i += HID) g_pooled[i] = 0.f;
        if (c < G_GRAPHS) g_cnt[c] = 0.f;
    }
}

// ---------------- CSR build: histogram ----------------------------------------
__global__ void k_hist(const int* __restrict__ ei) {
    int stride = gridDim.x * blockDim.x;
    for (int e = blockIdx.x * blockDim.x + threadIdx.x; e < N_EDGES; e += stride)
        atomicAdd(&g_deg[ei[N_EDGES + e]], 1);
}

// ---------------- CSR build: foolproof single-block scan ----------------------
__global__ void k_scan() {
    __shared__ int s_part[1024];
    const int CHUNK = 49;   // 1024 * 49 = 50176 >= N_NODES
    int t = threadIdx.x;
    int lo = t * CHUNK;
    int hi = lo + CHUNK; if (hi > N_NODES) hi = N_NODES;
    int sum = 0;
    for (int i = lo; i < hi; i++) sum += g_deg[i];
    s_part[t] = sum;
    __syncthreads();
    if (t == 0) {
        int acc = 0;
        for (int k = 0; k < 1024; k++) {
            int v = s_part[k];
            s_part[k] = acc;
            acc += v;
        }
        g_rowptr[N_NODES] = acc;
    }
    __syncthreads();
    int run = s_part[t];
    for (int i = lo; i < hi; i++) {
        g_rowptr[i] = run;
        run += g_deg[i];
    }
}

// ---------------- CSR build: fill (rowptr base + fresh cursor offset) ---------
__global__ void k_fill(const int* __restrict__ ei) {
    int stride = gridDim.x * blockDim.x;
    for (int e = blockIdx.x * blockDim.x + threadIdx.x; e < N_EDGES; e += stride) {
        int s = ei[e];
        int d = ei[N_EDGES + e];
        int pos = atomicAdd(&g_cursor[d], 1);
        g_csr_src[g_rowptr[d] + pos] = s;
    }
}

// ---------------- fused GATv2 edge pass, CSR form -----------------------------
// One warp per destination node. Lanes hold 4 channels each (ch = lane*4+k);
// lanes 0-15 = head 0, 16-31 = head 1. Softmax max-shift skipped (scores O(1)):
// identical alpha after normalization. Output selected INSIDE device code
// (passing __device__ symbols as host-side kernel args was the R4/R5 bug).
__global__ void k_edge_csr(const float* __restrict__ att,
                           const float* __restrict__ bias, int layer) {
    __shared__ float sm_s[8 * 128];
    __shared__ float sm_q[8 * 128];
    float* out = layer ? g_acc2 : g_acc1;
    int lane = threadIdx.x & 31;
    int wib = threadIdx.x >> 5;
    int node = blockIdx.x * 8 + wib;   // grid is exactly N_NODES/8 blocks

    float4 w = *(const float4*)&att[lane * 4];
    float4 b = *(const float4*)&g_xr[node * HID + lane * 4];
    float ax = 0.f, ay = 0.f, az = 0.f, aw = 0.f;
    float denom = 0.f;

#define PROCESS(a)                                                              \
    {                                                                           \
        float m0 = a.x + b.x, m1 = a.y + b.y, m2 = a.z + b.z, m3 = a.w + b.w;   \
        m0 = m0 > 0.f ? m0 : NEG_SLOPE * m0;                                    \
        m1 = m1 > 0.f ? m1 : NEG_SLOPE * m1;                                    \
        m2 = m2 > 0.f ? m2 : NEG_SLOPE * m2;                                    \
        m3 = m3 > 0.f ? m3 : NEG_SLOPE * m3;                                    \
        float part = m0 * w.x + m1 * w.y + m2 * w.z + m3 * w.w;                 \
        part += __shfl_xor_sync(0xffffffffu, part, 8);                          \
        part += __shfl_xor_sync(0xffffffffu, part, 4);                          \
        part += __shfl_xor_sync(0xffffffffu, part, 2);                          \
        part += __shfl_xor_sync(0xffffffffu, part, 1);                          \
        float p = __expf(part);                                                 \
        ax = fmaf(p, a.x, ax); ay = fmaf(p, a.y, ay);                           \
        az = fmaf(p, a.z, az); aw = fmaf(p, a.w, aw);                           \
        denom += p;                                                             \
    }

    // self loop
    {
        float4 a = *(const float4*)&g_xl[node * HID + lane * 4];
        PROCESS(a);
    }

    int beg = g_rowptr[node];
    int end = g_rowptr[node + 1];
    float4 a_n = make_float4(0.f, 0.f, 0.f, 0.f);
    if (beg < end) {
        int s = g_csr_src[beg];
        a_n = *(const float4*)&g_xl[s * HID + lane * 4];
    }
    for (int j = beg; j < end; j++) {
        float4 a = a_n;
        if (j + 1 < end) {
            int s = g_csr_src[j + 1];
            a_n = *(const float4*)&g_xl[s * HID + lane * 4];
        }
        PROCESS(a);
    }
#undef PROCESS

    float inv = __fdividef(1.f, denom);
    float4 bi = *(const float4*)&bias[lane * 4];
    float v0 = fmaf(ax, inv, bi.x);
    float v1 = fmaf(ay, inv, bi.y);
    float v2 = fmaf(az, inv, bi.z);
    float v3 = fmaf(aw, inv, bi.w);
    *(float4*)&out[node * HID + lane * 4] = make_float4(v0, v1, v2, v3);

    // BN stats: per-warp values -> block reduce -> global reduction adds
    int chb = lane * 4;
    sm_s[wib * 128 + chb + 0] = v0;  sm_q[wib * 128 + chb + 0] = v0 * v0;
    sm_s[wib * 128 + chb + 1] = v1;  sm_q[wib * 128 + chb + 1] = v1 * v1;
    sm_s[wib * 128 + chb + 2] = v2;  sm_q[wib * 128 + chb + 2] = v2 * v2;
    sm_s[wib * 128 + chb + 3] = v3;  sm_q[wib * 128 + chb + 3] = v3 * v3;
    __syncthreads();
    if (threadIdx.x < 128) {
        int c = threadIdx.x;
        float s = 0.f, q = 0.f;
        #pragma unroll
        for (int t = 0; t < 8; t++) {
            s += sm_s[t * 128 + c];
            q += sm_q[t * 128 + c];
        }
        atomicAdd(&g_sums[c], s);
        atomicAdd(&g_sumsq[c], q);
    }
}

// ---------------- BN prep: compute scale/shift, re-zero stats ----------------
__global__ void k_bn_prep(const float* __restrict__ gamma,
                          const float* __restrict__ beta) {
    int c = threadIdx.x; // 128
    const float invN = 1.f / (float)N_NODES;
    float mu  = g_sums[c] * invN;
    float var = g_sumsq[c] * invN - mu * mu;
    float sc  = gamma[c] * rsqrtf(var + BN_EPS);
    g_bn_sc[c] = sc;
    g_bn_sh[c] = beta[c] - mu * sc;
    g_sums[c] = 0.f;
    g_sumsq[c] = 0.f;
}

// ---------------- layer-2 transforms with fused BN1+ReLU on the A load -------
// [g_xl | g_xr] = relu(bn(g_acc1)) @ [Wl2 | Wr2]
__global__ void k_gemm2(const float* __restrict__ Wl,
                        const float* __restrict__ Wr) {
    __shared__ __align__(16) float sA[32][68];    // [k][row], padded
    __shared__ __align__(16) float wTd[32][256];  // [k][col duplicated pairs]

    int tid = threadIdx.x;
    int row0 = blockIdx.x * 64;
    const float* W = blockIdx.y ? Wr : Wl;
    float* dst = blockIdx.y ? g_xr : g_xl;

    int cg = tid & 31;   // 32 col groups of 4
    int rg = tid >> 5;   // 8 row groups of 8
    int c0 = cg * 4;
    int rg8 = rg * 8;

    unsigned long long acc[4][4];
    #pragma unroll
    for (int i = 0; i < 4; i++)
        #pragma unroll
        for (int j = 0; j < 4; j++) acc[i][j] = 0ull;

    for (int k0 = 0; k0 < HID; k0 += 32) {
        #pragma unroll
        for (int half = 0; half < 2; half++) {
            int u = tid + half * 256;
            int r = u >> 3;             // 0..63
            int k4 = (u & 7) * 4;
            int row = row0 + r;
            int rr = row < N_NODES ? row : N_NODES - 1;
            float4 v = *(const float4*)&g_acc1[rr * HID + k0 + k4];
            float4 sc = *(const float4*)&g_bn_sc[k0 + k4];
            float4 sh = *(const float4*)&g_bn_sh[k0 + k4];
            float t0 = fmaf(v.x, sc.x, sh.x); t0 = t0 > 0.f ? t0 : 0.f;
            float t1 = fmaf(v.y, sc.y, sh.y); t1 = t1 > 0.f ? t1 : 0.f;
            float t2 = fmaf(v.z, sc.z, sh.z); t2 = t2 > 0.f ? t2 : 0.f;
            float t3 = fmaf(v.w, sc.w, sh.w); t3 = t3 > 0.f ? t3 : 0.f;
            sA[k4 + 0][r] = t0;
            sA[k4 + 1][r] = t1;
            sA[k4 + 2][r] = t2;
            sA[k4 + 3][r] = t3;
        }
        #pragma unroll
        for (int i = 0; i < 4; i++) {
            int u = tid + i * 256;
            int kk = u >> 5;
            int c4 = (u & 31) * 4;
            float4 w = *(const float4*)&W[(k0 + kk) * HID + c4];
            *(float4*)&wTd[kk][c4 * 2]     = make_float4(w.x, w.x, w.y, w.y);
            *(float4*)&wTd[kk][c4 * 2 + 4] = make_float4(w.z, w.z, w.w, w.w);
        }
        __syncthreads();
        #pragma unroll
        for (int kk = 0; kk < 32; kk++) {
            ulonglong2 A0 = *(ulonglong2*)&sA[kk][rg8];
            ulonglong2 A1 = *(ulonglong2*)&sA[kk][rg8 + 4];
            ulonglong2 B0 = *(ulonglong2*)&wTd[kk][c0 * 2];
            ulonglong2 B1 = *(ulonglong2*)&wTd[kk][c0 * 2 + 4];
            FMA2(acc[0][0], A0.x, B0.x, acc[0][0]);
            FMA2(acc[0][1], A0.x, B0.y, acc[0][1]);
            FMA2(acc[0][2], A0.x, B1.x, acc[0][2]);
            FMA2(acc[0][3], A0.x, B1.y, acc[0][3]);
            FMA2(acc[1][0], A0.y, B0.x, acc[1][0]);
            FMA2(acc[1][1], A0.y, B0.y, acc[1][1]);
            FMA2(acc[1][2], A0.y, B1.x, acc[1][2]);
            FMA2(acc[1][3], A0.y, B1.y, acc[1][3]);
            FMA2(acc[2][0], A1.x, B0.x, acc[2][0]);
            FMA2(acc[2][1], A1.x, B0.y, acc[2][1]);
            FMA2(acc[2][2], A1.x, B1.x, acc[2][2]);
            FMA2(acc[2][3], A1.x, B1.y, acc[2][3]);
            FMA2(acc[3][0], A1.y, B0.x, acc[3][0]);
            FMA2(acc[3][1], A1.y, B0.y, acc[3][1]);
            FMA2(acc[3][2], A1.y, B1.x, acc[3][2]);
            FMA2(acc[3][3], A1.y, B1.y, acc[3][3]);
        }
        __syncthreads();
    }

    #pragma unroll
    for (int rp = 0; rp < 4; rp++) {
        F2U p0, p1, p2, p3;
        p0.u = acc[rp][0]; p1.u = acc[rp][1];
        p2.u = acc[rp][2]; p3.u = acc[rp][3];
        int row_e = row0 + rg8 + rp * 2;
        if (row_e < N_NODES)
            *(float4*)&dst[row_e * HID + c0] =
                make_float4(p0.f.x, p1.f.x, p2.f.x, p3.f.x);
        if (row_e + 1 < N_NODES)
            *(float4*)&dst[(row_e + 1) * HID + c0] =
                make_float4(p0.f.y, p1.f.y, p2.f.y, p3.f.y);
    }
}

// ---------------- global mean pool with fused BN2 + ReLU ---------------------
__global__ void k_pool(const int* __restrict__ batch) {
    int gwarp = (blockIdx.x * blockDim.x + threadIdx.x) >> 5;
    int nwarps = (gridDim.x * blockDim.x) >> 5;
    int lane = threadIdx.x & 31;
    float4 sc = *(const float4*)&g_bn_sc[lane * 4];
    float4 sh = *(const float4*)&g_bn_sh[lane * 4];
    for (int n = gwarp; n < N_NODES; n += nwarps) {
        int g = __ldg(&batch[n]);
        float4 v = *(const float4*)&g_acc2[n * HID + lane * 4];
        float v0 = fmaf(v.x, sc.x, sh.x); v0 = v0 > 0.f ? v0 : 0.f;
        float v1 = fmaf(v.y, sc.y, sh.y); v1 = v1 > 0.f ? v1 : 0.f;
        float v2 = fmaf(v.z, sc.z, sh.z); v2 = v2 > 0.f ? v2 : 0.f;
        float v3 = fmaf(v.w, sc.w, sh.w); v3 = v3 > 0.f ? v3 : 0.f;
        float* dptr = &g_pooled[g * HID + lane * 4];
        asm volatile("red.global.add.v4.f32 [%0], {%1,%2,%3,%4};"
                     :: "l"(dptr), "f"(v0), "f"(v1), "f"(v2), "f"(v3)
                     : "memory");
        if (lane == 0) atomicAdd(&g_cnt[g], 1.f);
    }
}

// ---------------- MLP head ----------------------------------------------------
__global__ void k_head(const float* __restrict__ W3, const float* __restrict__ b3,
                       const float* __restrict__ W4, const float* __restrict__ b4,
                       float* __restrict__ out) {
    __shared__ float z[CH];
    int g = blockIdx.x;   // 64 graphs
    int t = threadIdx.x;  // 64 threads
    float cnt = g_cnt[g];
    float inv = 1.f / (cnt > 1.f ? cnt : 1.f);
    float a = b3[t];
    #pragma unroll 4
    for (int k = 0; k < HID; k++)
        a += (g_pooled[g * HID + k] * inv) * W3[k * CH + t];
    z[t] = a > 0.f ? a : 0.f;
    __syncthreads();
    if (t < OUT_DIM) {
        float o = b4[t];
        #pragma unroll
        for (int k = 0; k < CH; k++)
            o += z[k] * W4[k * OUT_DIM + t];
        out[g * OUT_DIM + t] = o;
    }
}

// ---------------- launch ------------------------------------------------------
extern "C" void kernel_launch(void* const* d_in, const int* in_sizes, int n_in,
                              void* d_out, int out_size) {
    const float* x     = (const float*)d_in[0];
    const int*   ei    = (const int*)d_in[1];    // int32 (JAX x64 disabled)
    const int*   batch = (const int*)d_in[2];
    const float* Wl1 = (const float*)d_in[3];
    const float* Wr1 = (const float*)d_in[4];
    const float* att1= (const float*)d_in[5];
    const float* b1  = (const float*)d_in[6];
    const float* g1  = (const float*)d_in[7];
    const float* be1 = (const float*)d_in[8];
    const float* Wl2 = (const float*)d_in[9];
    const float* Wr2 = (const float*)d_in[10];
    const float* att2= (const float*)d_in[11];
    const float* b2  = (const float*)d_in[12];
    const float* g2  = (const float*)d_in[13];
    const float* be2 = (const float*)d_in[14];
    const float* W3  = (const float*)d_in[15];
    const float* b3  = (const float*)d_in[16];
    const float* W4  = (const float*)d_in[17];
    const float* b4  = (const float*)d_in[18];
    float* out = (float*)d_out;

    // ---- transforms + CSR build (CSR shared by both layers) ----
    k_transform1<<<2048, 128>>>(x, Wl1, Wr1);
    k_hist<<<1600, 512>>>(ei);
    k_scan<<<1, 1024>>>();
    k_fill<<<1600, 512>>>(ei);

    // ---- layer 1 (fully fused edge pass) ----
    k_edge_csr<<<N_NODES / 8, 256>>>(att1, b1, 0);
    k_bn_prep<<<1, 128>>>(g1, be1);

    // ---- layer 2 transforms (BN1+ReLU fused into A load) ----
    dim3 ggrid((N_NODES + 63) / 64, 2);
    k_gemm2<<<ggrid, 256>>>(Wl2, Wr2);

    // ---- layer 2 ----
    k_edge_csr<<<N_NODES / 8, 256>>>(att2, b2, 1);
    k_bn_prep<<<1, 128>>>(g2, be2);

    // ---- pool + head (BN2+ReLU fused into pool) ----
    k_pool<<<512, 256>>>(batch);
    k_head<<<G_GRAPHS, CH>>>(W3, b3, W4, b4, out);
}